// round 2
// baseline (speedup 1.0000x reference)
#include <cuda_runtime.h>
#include <math.h>

#define BB 256
#define FF 512
#define CC 100000
#define SSC 64.0f
#define MMAR 0.4f
#define KVP 0.7f

// scratch (__device__ globals: no allocations allowed)
__device__ float g_emb[BB * FF];
__device__ float g_newq[BB * FF];   // normalized updated queue rows (per b)
__device__ float g_oldn[BB * FF];   // normalized old queue rows at labels (per b)
__device__ float g_rowsum1[BB];
__device__ float g_rowsum2[BB];
__device__ float g_pos1[BB];
__device__ float g_pos2[BB];
__device__ int   g_owner[BB];

// ---------------------------------------------------------------------------
// K1: normalize input rows (eps 1e-5), zero accumulators
__global__ void k_norm_input(const float* __restrict__ inp) {
    int b = blockIdx.x, t = threadIdx.x;  // 128 threads
    __shared__ float red[128];
    float s = 0.f;
    for (int k = t; k < FF; k += 128) { float v = inp[b * FF + k]; s += v * v; }
    red[t] = s; __syncthreads();
    for (int o = 64; o > 0; o >>= 1) { if (t < o) red[t] += red[t + o]; __syncthreads(); }
    float inv = 1.f / fmaxf(sqrtf(red[0]), 1e-5f);
    for (int k = t; k < FF; k += 128) g_emb[b * FF + k] = inp[b * FF + k] * inv;
    if (t == 0) { g_rowsum1[b] = 0.f; g_rowsum2[b] = 0.f; }
}

// ---------------------------------------------------------------------------
// K2: virtual-prototype update for the 256 labeled rows (reads only; queue untouched)
__global__ void k_queue_update(const float* __restrict__ queue, const int* __restrict__ label) {
    int b = blockIdx.x, t = threadIdx.x;  // 128 threads
    int lb = label[b];
    const float* q = queue + (size_t)lb * FF;
    const float* e = g_emb + b * FF;
    __shared__ float r1[128], r2[128];
    float sq = 0.f, dd = 0.f;
    for (int k = t; k < FF; k += 128) { float qa = q[k], ea = e[k]; sq += qa * qa; dd += qa * ea; }
    r1[t] = sq; r2[t] = dd; __syncthreads();
    for (int o = 64; o > 0; o >>= 1) {
        if (t < o) { r1[t] += r1[t + o]; r2[t] += r2[t + o]; }
        __syncthreads();
    }
    float invold = 1.f / fmaxf(sqrtf(r1[0]), 1e-12f);
    float drift = r2[0];
    float factor = drift / (1.f + fabsf(drift));  // softsign
    __syncthreads();
    float sn = 0.f;
    for (int k = t; k < FF; k += 128) {
        float v = factor * q[k] + (1.f - factor) * e[k];
        sn += v * v;
    }
    r1[t] = sn; __syncthreads();
    for (int o = 64; o > 0; o >>= 1) { if (t < o) r1[t] += r1[t + o]; __syncthreads(); }
    float invnew = 1.f / fmaxf(sqrtf(r1[0]), 1e-12f);
    for (int k = t; k < FF; k += 128) {
        float v = factor * q[k] + (1.f - factor) * e[k];
        g_newq[b * FF + k] = v * invnew;
        g_oldn[b * FF + k] = q[k] * invold;
    }
    if (t == 0) {
        int own = 1;  // scatter: last occurrence wins
        for (int j = b + 1; j < BB; j++) if (label[j] == lb) { own = 0; break; }
        g_owner[b] = own;
    }
}

// ---------------------------------------------------------------------------
// K3/K4: fused GEMM (256 x 64 tile over K=512) + row-norm of W + exp + row-sum.
// LS=true : weight pass (label col -> pos1, excluded from neg sum), eps 1e-5
// LS=false: queue pass (everything summed; labeled cols fixed up by k_correct), eps 1e-12
template <bool LS>
__global__ __launch_bounds__(256) void k_gemm_exp(const float* __restrict__ W, const int* __restrict__ label) {
    __shared__ float As[16][256];
    __shared__ float Bs[16][64];
    __shared__ float nsq[64];
    __shared__ int   slab[256];

    int tid = threadIdx.x;
    int c0 = blockIdx.x * 64;
    if (tid < 64) nsq[tid] = 0.f;
    slab[tid] = label[tid];

    float acc[8][8];
#pragma unroll
    for (int i = 0; i < 8; i++)
#pragma unroll
        for (int j = 0; j < 8; j++) acc[i][j] = 0.f;

    int bn = tid >> 2;            // 0..63 class within tile
    int bkk = (tid & 3) * 4;      // k sub-offset
    int mi = (tid >> 3) << 3;     // row base 0..248
    int ni = (tid & 7) << 3;      // col base 0..56

    for (int k0 = 0; k0 < FF; k0 += 16) {
        // A: one emb row per thread (L2-resident)
        const float4* ar = (const float4*)(g_emb + (size_t)tid * FF + k0);
        float4 a0 = ar[0], a1 = ar[1], a2 = ar[2], a3 = ar[3];
        // B: 64 classes x 16 k
        int c = c0 + bn;
        float4 bv = make_float4(0.f, 0.f, 0.f, 0.f);
        if (c < CC) bv = *(const float4*)(W + (size_t)c * FF + k0 + bkk);

        __syncthreads();  // previous tile fully consumed
        As[0][tid] = a0.x;  As[1][tid] = a0.y;  As[2][tid] = a0.z;  As[3][tid] = a0.w;
        As[4][tid] = a1.x;  As[5][tid] = a1.y;  As[6][tid] = a1.z;  As[7][tid] = a1.w;
        As[8][tid] = a2.x;  As[9][tid] = a2.y;  As[10][tid] = a2.z; As[11][tid] = a2.w;
        As[12][tid] = a3.x; As[13][tid] = a3.y; As[14][tid] = a3.z; As[15][tid] = a3.w;
        Bs[bkk + 0][bn] = bv.x; Bs[bkk + 1][bn] = bv.y;
        Bs[bkk + 2][bn] = bv.z; Bs[bkk + 3][bn] = bv.w;
        atomicAdd(&nsq[bn], bv.x * bv.x + bv.y * bv.y + bv.z * bv.z + bv.w * bv.w);
        __syncthreads();

#pragma unroll
        for (int k = 0; k < 16; k++) {
            float4 A0 = *(float4*)&As[k][mi];
            float4 A1 = *(float4*)&As[k][mi + 4];
            float4 B0 = *(float4*)&Bs[k][ni];
            float4 B1 = *(float4*)&Bs[k][ni + 4];
            float am[8] = {A0.x, A0.y, A0.z, A0.w, A1.x, A1.y, A1.z, A1.w};
            float bb[8] = {B0.x, B0.y, B0.z, B0.w, B1.x, B1.y, B1.z, B1.w};
#pragma unroll
            for (int i = 0; i < 8; i++)
#pragma unroll
                for (int j = 0; j < 8; j++) acc[i][j] += am[i] * bb[j];
        }
    }
    __syncthreads();

    // epilogue: cos -> exp -> per-row partial sums
    float rp[8];
#pragma unroll
    for (int i = 0; i < 8; i++) rp[i] = 0.f;
    float eps = LS ? 1e-5f : 1e-12f;
#pragma unroll
    for (int j = 0; j < 8; j++) {
        int c = c0 + ni + j;
        if (c >= CC) continue;
        float iv = 1.f / fmaxf(sqrtf(nsq[ni + j]), eps);
#pragma unroll
        for (int i = 0; i < 8; i++) {
            float cosv = acc[i][j] * iv;
            int m = mi + i;
            if (LS && c == slab[m]) {
                g_pos1[m] = __expf(-SSC * (cosv - MMAR));  // positive term, excluded from neg
            } else {
                rp[i] += __expf(SSC * cosv);
            }
        }
    }
    float* rowsum = LS ? g_rowsum1 : g_rowsum2;
#pragma unroll
    for (int i = 0; i < 8; i++) {
        float v = rp[i];
        v += __shfl_down_sync(0xffffffffu, v, 4, 8);
        v += __shfl_down_sync(0xffffffffu, v, 2, 8);
        v += __shfl_down_sync(0xffffffffu, v, 1, 8);
        if ((tid & 7) == 0) atomicAdd(&rowsum[mi + i], v);
    }
}

// ---------------------------------------------------------------------------
// K5: fix up the <=256 modified queue columns: remove old-row exp terms, add
// new-row exp terms; diag column produces pos2 (positive term uses 0.3*diag).
__global__ void k_correct(const int* __restrict__ label) {
    int b = blockIdx.x;          // one row per block
    int tid = threadIdx.x;       // 256 = 8 warps
    int w = tid >> 5, lane = tid & 31;
    __shared__ float es[FF];
    __shared__ float wsum[8];
    for (int k = tid; k < FF; k += 256) es[k] = g_emb[b * FF + k];
    __syncthreads();
    int mylab = label[b];
    float negd = 0.f;
    for (int j = w; j < BB; j += 8) {
        if (!g_owner[j]) continue;  // uniform per warp
        float d_old = 0.f, d_new = 0.f;
        const float* po = g_oldn + (size_t)j * FF;
        const float* pn = g_newq + (size_t)j * FF;
        for (int k = lane; k < FF; k += 32) {
            float e = es[k];
            d_old += e * po[k];
            d_new += e * pn[k];
        }
#pragma unroll
        for (int o = 16; o > 0; o >>= 1) {
            d_old += __shfl_down_sync(0xffffffffu, d_old, o);
            d_new += __shfl_down_sync(0xffffffffu, d_new, o);
        }
        if (lane == 0) {
            negd -= __expf(SSC * d_old);          // remove old-row contribution
            if (label[j] == mylab) {
                // diag' = diag - KVP*stop_grad(diag) = (1-KVP)*diag; pos term = exp(-s*diag')
                g_pos2[b] = __expf(-SSC * (1.f - KVP) * d_new);
            } else {
                negd += __expf(SSC * d_new);      // updated row as negative
            }
        }
    }
    if (lane == 0) wsum[w] = negd;
    __syncthreads();
    if (tid == 0) {
        float s = 0.f;
        for (int i = 0; i < 8; i++) s += wsum[i];
        atomicAdd(&g_rowsum2[b], s);
    }
}

// ---------------------------------------------------------------------------
// K6: EPL loss: mean over 2B rows of log1p(sum_neg * sum_pos)
__global__ void k_final(float* __restrict__ out) {
    int t = threadIdx.x;  // 256
    __shared__ float red[256];
    float v = log1pf(g_rowsum1[t] * g_pos1[t]) + log1pf(g_rowsum2[t] * g_pos2[t]);
    red[t] = v; __syncthreads();
    for (int o = 128; o > 0; o >>= 1) { if (t < o) red[t] += red[t + o]; __syncthreads(); }
    if (t == 0) out[0] = red[0] / (2.f * BB);
}

// ---------------------------------------------------------------------------
extern "C" void kernel_launch(void* const* d_in, const int* in_sizes, int n_in,
                              void* d_out, int out_size) {
    const float* inp    = (const float*)d_in[0];
    const float* weight = (const float*)d_in[1];
    const float* queue  = (const float*)d_in[2];
    const int*   label  = (const int*)d_in[3];
    // d_in[4] = epoch (always takes the vp branch for epoch=5)
    float* out = (float*)d_out;

    k_norm_input<<<BB, 128>>>(inp);
    k_queue_update<<<BB, 128>>>(queue, label);
    int gb = (CC + 63) / 64;
    k_gemm_exp<true><<<gb, 256>>>(weight, label);
    k_gemm_exp<false><<<gb, 256>>>(queue, label);
    k_correct<<<BB, 256>>>(label);
    k_final<<<1, 256>>>(out);
}

// round 4
// speedup vs baseline: 3.9789x; 3.9789x over previous
#include <cuda_runtime.h>
#include <cuda_bf16.h>
#include <cstdint>
#include <math.h>

#define BB 256
#define FF 512
#define CC 100000
#define SSC 64.0f
#define MMAR 0.4f
#define KVP 0.7f

#define BM 128
#define BN 128
#define KC 64
#define NCH (FF / KC)                 // 8
#define NTILES ((CC + BN - 1) / BN)   // 782
#define STR 72                        // padded smem stride (elems) -> conflict-free ldmatrix

__device__ float g_emb[BB * FF];
__device__ __nv_bfloat16 g_embh[BB * FF];
__device__ float g_newq[BB * FF];
__device__ float g_oldn[BB * FF];
__device__ float g_rowsum1[BB];
__device__ float g_rowsum2[BB];
__device__ float g_pos1[BB];
__device__ float g_pos2[BB];
__device__ int   g_owner[BB];

static __device__ __forceinline__ uint32_t s2u(const void* p) {
    uint32_t a;
    asm("{ .reg .u64 t; cvta.to.shared.u64 t, %1; cvt.u32.u64 %0, t; }" : "=r"(a) : "l"(p));
    return a;
}

#define LDSM4(r0, r1, r2, r3, addr) \
    asm volatile("ldmatrix.sync.aligned.m8n8.x4.shared.b16 {%0,%1,%2,%3}, [%4];" \
                 : "=r"(r0), "=r"(r1), "=r"(r2), "=r"(r3) : "r"(addr))

#define MMA16816(d, a, b) \
    asm volatile("mma.sync.aligned.m16n8k16.row.col.f32.bf16.bf16.f32 " \
                 "{%0,%1,%2,%3},{%4,%5,%6,%7},{%8,%9},{%0,%1,%2,%3};" \
                 : "+f"((d)[0]), "+f"((d)[1]), "+f"((d)[2]), "+f"((d)[3]) \
                 : "r"((a)[0]), "r"((a)[1]), "r"((a)[2]), "r"((a)[3]), \
                   "r"((b)[0]), "r"((b)[1]))

static __device__ __forceinline__ uint32_t pk(float x, float y) {
    __nv_bfloat162 h = __floats2bfloat162_rn(x, y);
    return *(uint32_t*)&h;
}

// ---------------------------------------------------------------------------
// K1: normalize input rows (eps 1e-5), fp32 + bf16 copies, zero accumulators
__global__ void k_norm_input(const float* __restrict__ inp) {
    int b = blockIdx.x, t = threadIdx.x;  // 128 threads
    __shared__ float red[128];
    float s = 0.f;
    for (int k = t; k < FF; k += 128) { float v = inp[b * FF + k]; s += v * v; }
    red[t] = s; __syncthreads();
    for (int o = 64; o > 0; o >>= 1) { if (t < o) red[t] += red[t + o]; __syncthreads(); }
    float inv = 1.f / fmaxf(sqrtf(red[0]), 1e-5f);
    for (int k = t; k < FF; k += 128) {
        float e = inp[b * FF + k] * inv;
        g_emb[b * FF + k] = e;
        g_embh[b * FF + k] = __float2bfloat16(e);
    }
    if (t == 0) { g_rowsum1[b] = 0.f; g_rowsum2[b] = 0.f; }
}

// ---------------------------------------------------------------------------
// K2: virtual-prototype update for the 256 labeled rows (queue untouched)
__global__ void k_queue_update(const float* __restrict__ queue, const int* __restrict__ label) {
    int b = blockIdx.x, t = threadIdx.x;  // 128 threads
    int lb = label[b];
    const float* q = queue + (size_t)lb * FF;
    const float* e = g_emb + b * FF;
    __shared__ float r1[128], r2[128];
    float sq = 0.f, dd = 0.f;
    for (int k = t; k < FF; k += 128) { float qa = q[k], ea = e[k]; sq += qa * qa; dd += qa * ea; }
    r1[t] = sq; r2[t] = dd; __syncthreads();
    for (int o = 64; o > 0; o >>= 1) {
        if (t < o) { r1[t] += r1[t + o]; r2[t] += r2[t + o]; }
        __syncthreads();
    }
    float invold = 1.f / fmaxf(sqrtf(r1[0]), 1e-12f);
    float drift = r2[0];
    float factor = drift / (1.f + fabsf(drift));
    __syncthreads();
    float sn = 0.f;
    for (int k = t; k < FF; k += 128) {
        float v = factor * q[k] + (1.f - factor) * e[k];
        sn += v * v;
    }
    r1[t] = sn; __syncthreads();
    for (int o = 64; o > 0; o >>= 1) { if (t < o) r1[t] += r1[t + o]; __syncthreads(); }
    float invnew = 1.f / fmaxf(sqrtf(r1[0]), 1e-12f);
    for (int k = t; k < FF; k += 128) {
        float v = factor * q[k] + (1.f - factor) * e[k];
        g_newq[b * FF + k] = v * invnew;
        g_oldn[b * FF + k] = q[k] * invold;
    }
    if (t == 0) {
        int own = 1;
        for (int j = b + 1; j < BB; j++) if (label[j] == lb) { own = 0; break; }
        g_owner[b] = own;
    }
}

// ---------------------------------------------------------------------------
// K3: HMMA GEMM with fused norm + exp + rowsum.  pass = blockIdx.z
//   pass 0: weight (eps 1e-5, label col -> pos1, excluded from neg sum)
//   pass 1: queue  (eps 1e-12, everything summed; k_correct fixes labeled cols)
__global__ void __launch_bounds__(512)
k_gemm(const float* __restrict__ Wt, const float* __restrict__ Qu, const int* __restrict__ label) {
    __shared__ __nv_bfloat16 As[BM * STR];
    __shared__ __nv_bfloat16 Bs[BN * STR];
    __shared__ float s_nsq[BN];
    __shared__ float s_invn[BN];
    __shared__ float s_row[BM];
    __shared__ int s_lab[BM];

    int pass = blockIdx.z;
    const float* W = pass ? Qu : Wt;
    int m0 = blockIdx.y * BM;
    int c0 = blockIdx.x * BN;
    int tid = threadIdx.x;
    int wid = tid >> 5, lane = tid & 31;
    int mw = wid >> 2, nw = wid & 3;     // 4x4 warp grid, 32x32 warp tile

    if (tid < BM) { s_row[tid] = 0.f; s_lab[tid] = label[m0 + tid]; }

    int lr = tid >> 2;                   // load row 0..127
    int lq = tid & 3;                    // quarter: 16 elems each
    int gBr = c0 + lr;
    bool bok = gBr < CC;

    float d[2][4][4];
#pragma unroll
    for (int i = 0; i < 2; i++)
#pragma unroll
        for (int j = 0; j < 4; j++)
#pragma unroll
            for (int e = 0; e < 4; e++) d[i][j][e] = 0.f;

    float ssacc = 0.f;
    uint32_t aAs = s2u(As), aBs = s2u(Bs);
    int rin = lane & 7, seg = lane >> 3;

    uint4 pa0, pa1;
    float4 pb[4];
    {   // prefetch chunk 0
        const uint4* p = (const uint4*)(g_embh + (size_t)(m0 + lr) * FF + lq * 16);
        pa0 = p[0]; pa1 = p[1];
        if (bok) {
            const float4* q = (const float4*)(W + (size_t)gBr * FF + lq * 16);
            pb[0] = q[0]; pb[1] = q[1]; pb[2] = q[2]; pb[3] = q[3];
        } else {
            pb[0] = pb[1] = pb[2] = pb[3] = make_float4(0.f, 0.f, 0.f, 0.f);
        }
    }

    for (int c = 0; c < NCH; c++) {
        __syncthreads();   // previous compute finished; smem reusable
        {   // store A
            uint4* pa = (uint4*)(As + lr * STR + lq * 16);
            pa[0] = pa0; pa[1] = pa1;
            // norm accum + convert + store B
            float ss = 0.f;
#pragma unroll
            for (int i = 0; i < 4; i++)
                ss += pb[i].x * pb[i].x + pb[i].y * pb[i].y + pb[i].z * pb[i].z + pb[i].w * pb[i].w;
            ssacc += ss;
            uint4 q0, q1;
            q0.x = pk(pb[0].x, pb[0].y); q0.y = pk(pb[0].z, pb[0].w);
            q0.z = pk(pb[1].x, pb[1].y); q0.w = pk(pb[1].z, pb[1].w);
            q1.x = pk(pb[2].x, pb[2].y); q1.y = pk(pb[2].z, pb[2].w);
            q1.z = pk(pb[3].x, pb[3].y); q1.w = pk(pb[3].z, pb[3].w);
            uint4* pbs = (uint4*)(Bs + lr * STR + lq * 16);
            pbs[0] = q0; pbs[1] = q1;
        }
        __syncthreads();
        if (c + 1 < NCH) {  // prefetch next chunk (overlaps compute below)
            const uint4* p = (const uint4*)(g_embh + (size_t)(m0 + lr) * FF + (c + 1) * KC + lq * 16);
            pa0 = p[0]; pa1 = p[1];
            if (bok) {
                const float4* q = (const float4*)(W + (size_t)gBr * FF + (c + 1) * KC + lq * 16);
                pb[0] = q[0]; pb[1] = q[1]; pb[2] = q[2]; pb[3] = q[3];
            }
        }
#pragma unroll
        for (int ks = 0; ks < 4; ks++) {
            int kk = ks * 16;
            uint32_t af[2][4];
#pragma unroll
            for (int mf = 0; mf < 2; mf++) {
                int row = mw * 32 + mf * 16 + (seg & 1) * 8 + rin;
                int col = kk + (seg >> 1) * 8;
                LDSM4(af[mf][0], af[mf][1], af[mf][2], af[mf][3],
                      aAs + (uint32_t)(row * STR + col) * 2);
            }
            uint32_t bfr[4][2];
#pragma unroll
            for (int bh = 0; bh < 2; bh++) {
                int row = nw * 32 + bh * 16 + (seg >> 1) * 8 + rin;
                int col = kk + (seg & 1) * 8;
                uint32_t r0, r1, r2, r3;
                LDSM4(r0, r1, r2, r3, aBs + (uint32_t)(row * STR + col) * 2);
                bfr[bh * 2][0] = r0;     bfr[bh * 2][1] = r1;
                bfr[bh * 2 + 1][0] = r2; bfr[bh * 2 + 1][1] = r3;
            }
#pragma unroll
            for (int mf = 0; mf < 2; mf++)
#pragma unroll
                for (int nt = 0; nt < 4; nt++) MMA16816(d[mf][nt], af[mf], bfr[nt]);
        }
    }

    // class norms: row lr loaded by lanes lq 0..3 (adjacent)
    ssacc += __shfl_xor_sync(0xffffffffu, ssacc, 1);
    ssacc += __shfl_xor_sync(0xffffffffu, ssacc, 2);
    if (lq == 0) s_nsq[lr] = ssacc;
    __syncthreads();
    if (tid < BN) s_invn[tid] = 1.f / fmaxf(sqrtf(s_nsq[tid]), pass ? 1e-12f : 1e-5f);
    __syncthreads();

    // epilogue
    int g4 = lane >> 2, j4 = lane & 3;
#pragma unroll
    for (int mf = 0; mf < 2; mf++) {
        int ra = mw * 32 + mf * 16 + g4;
        int rb = ra + 8;
        int la = s_lab[ra], lb = s_lab[rb];
        float sa = 0.f, sb = 0.f;
#pragma unroll
        for (int nt = 0; nt < 4; nt++) {
            int cbase = nw * 32 + nt * 8 + j4 * 2;
#pragma unroll
            for (int e = 0; e < 2; e++) {
                int lc = cbase + e;
                int gc = c0 + lc;
                if (gc < CC) {
                    float iv = s_invn[lc];
                    float cva = d[mf][nt][e] * iv;
                    if (pass == 0 && gc == la) g_pos1[m0 + ra] = __expf(-SSC * (cva - MMAR));
                    else sa += __expf(SSC * cva);
                    float cvb = d[mf][nt][e + 2] * iv;
                    if (pass == 0 && gc == lb) g_pos1[m0 + rb] = __expf(-SSC * (cvb - MMAR));
                    else sb += __expf(SSC * cvb);
                }
            }
        }
        sa += __shfl_xor_sync(0xffffffffu, sa, 1);
        sa += __shfl_xor_sync(0xffffffffu, sa, 2);
        sb += __shfl_xor_sync(0xffffffffu, sb, 1);
        sb += __shfl_xor_sync(0xffffffffu, sb, 2);
        if (j4 == 0) { atomicAdd(&s_row[ra], sa); atomicAdd(&s_row[rb], sb); }
    }
    __syncthreads();
    if (tid < BM)
        atomicAdd(pass ? &g_rowsum2[m0 + tid] : &g_rowsum1[m0 + tid], s_row[tid]);
}

// ---------------------------------------------------------------------------
// K5: fix up the <=256 modified queue columns
__global__ void k_correct(const int* __restrict__ label) {
    int b = blockIdx.x;
    int tid = threadIdx.x;  // 256 = 8 warps
    int w = tid >> 5, lane = tid & 31;
    __shared__ float es[FF];
    __shared__ float wsum[8];
    for (int k = tid; k < FF; k += 256) es[k] = g_emb[b * FF + k];
    __syncthreads();
    int mylab = label[b];
    float negd = 0.f;
    for (int j = w; j < BB; j += 8) {
        if (!g_owner[j]) continue;
        float d_old = 0.f, d_new = 0.f;
        const float* po = g_oldn + (size_t)j * FF;
        const float* pn = g_newq + (size_t)j * FF;
        for (int k = lane; k < FF; k += 32) {
            float e = es[k];
            d_old += e * po[k];
            d_new += e * pn[k];
        }
#pragma unroll
        for (int o = 16; o > 0; o >>= 1) {
            d_old += __shfl_down_sync(0xffffffffu, d_old, o);
            d_new += __shfl_down_sync(0xffffffffu, d_new, o);
        }
        if (lane == 0) {
            negd -= __expf(SSC * d_old);
            if (label[j] == mylab) {
                g_pos2[b] = __expf(-SSC * (1.f - KVP) * d_new);
            } else {
                negd += __expf(SSC * d_new);
            }
        }
    }
    if (lane == 0) wsum[w] = negd;
    __syncthreads();
    if (tid == 0) {
        float s = 0.f;
        for (int i = 0; i < 8; i++) s += wsum[i];
        atomicAdd(&g_rowsum2[b], s);
    }
}

// ---------------------------------------------------------------------------
// K6: EPL loss
__global__ void k_final(float* __restrict__ out) {
    int t = threadIdx.x;  // 256
    __shared__ float red[256];
    float v = log1pf(g_rowsum1[t] * g_pos1[t]) + log1pf(g_rowsum2[t] * g_pos2[t]);
    red[t] = v; __syncthreads();
    for (int o = 128; o > 0; o >>= 1) { if (t < o) red[t] += red[t + o]; __syncthreads(); }
    if (t == 0) out[0] = red[0] / (2.f * BB);
}

// ---------------------------------------------------------------------------
extern "C" void kernel_launch(void* const* d_in, const int* in_sizes, int n_in,
                              void* d_out, int out_size) {
    const float* inp    = (const float*)d_in[0];
    const float* weight = (const float*)d_in[1];
    const float* queue  = (const float*)d_in[2];
    const int*   label  = (const int*)d_in[3];
    float* out = (float*)d_out;

    k_norm_input<<<BB, 128>>>(inp);
    k_queue_update<<<BB, 128>>>(queue, label);
    dim3 grid(NTILES, BB / BM, 2);
    k_gemm<<<grid, 512>>>(weight, queue, label);
    k_correct<<<BB, 256>>>(label);
    k_final<<<1, 256>>>(out);
}

// round 5
// speedup vs baseline: 4.5496x; 1.1434x over previous
#include <cuda_runtime.h>
#include <cuda_bf16.h>
#include <cstdint>
#include <math.h>

#define BB 256
#define FF 512
#define CC 100000
#define SSC 64.0f
#define MMAR 0.4f
#define KVP 0.7f

#define BM 128
#define BN 128
#define KC 64
#define NCH (FF / KC)                 // 8
#define NTILES ((CC + BN - 1) / BN)   // 782
#define STR 72                        // padded smem stride (elems) -> conflict-free ldmatrix

#define KE 92.33248261972343f         // SSC * log2(e)

__device__ float g_emb[BB * FF];
__device__ __nv_bfloat16 g_embh[BB * FF];
__device__ float g_newq[BB * FF];
__device__ float g_oldn[BB * FF];
__device__ float g_rowsum1[BB];
__device__ float g_rowsum2[BB];
__device__ float g_pos1[BB];
__device__ float g_pos2[BB];
__device__ int   g_owner[BB];

static __device__ __forceinline__ uint32_t s2u(const void* p) {
    uint32_t a;
    asm("{ .reg .u64 t; cvta.to.shared.u64 t, %1; cvt.u32.u64 %0, t; }" : "=r"(a) : "l"(p));
    return a;
}

#define LDSM4(r0, r1, r2, r3, addr) \
    asm volatile("ldmatrix.sync.aligned.m8n8.x4.shared.b16 {%0,%1,%2,%3}, [%4];" \
                 : "=r"(r0), "=r"(r1), "=r"(r2), "=r"(r3) : "r"(addr))

#define MMA16816(d, a, b) \
    asm volatile("mma.sync.aligned.m16n8k16.row.col.f32.bf16.bf16.f32 " \
                 "{%0,%1,%2,%3},{%4,%5,%6,%7},{%8,%9},{%0,%1,%2,%3};" \
                 : "+f"((d)[0]), "+f"((d)[1]), "+f"((d)[2]), "+f"((d)[3]) \
                 : "r"((a)[0]), "r"((a)[1]), "r"((a)[2]), "r"((a)[3]), \
                   "r"((b)[0]), "r"((b)[1]))

static __device__ __forceinline__ uint32_t pk(float x, float y) {
    __nv_bfloat162 h = __floats2bfloat162_rn(x, y);
    return *(uint32_t*)&h;
}

// fast 2^y on the fma/alu pipes (no MUFU). |y| <= ~126. err ~2e-9.
static __device__ __forceinline__ float fexp2(float y) {
    float t = y + 12582912.f;              // round-to-nearest int in low mantissa bits
    int i = __float_as_int(t);
    float f = y - (t - 12582912.f);        // f in [-0.5, 0.5]
    float p = 1.5403530e-4f;
    p = fmaf(p, f, 1.3333558e-3f);
    p = fmaf(p, f, 9.6181291e-3f);
    p = fmaf(p, f, 5.5504109e-2f);
    p = fmaf(p, f, 2.4022651e-1f);
    p = fmaf(p, f, 6.9314718e-1f);
    p = fmaf(p, f, 1.0f);
    return __int_as_float((i << 23) + 0x3f800000) * p;
}

// ---------------------------------------------------------------------------
// K1: normalize input rows (eps 1e-5), fp32 + bf16 copies, zero accumulators
__global__ void k_norm_input(const float* __restrict__ inp) {
    int b = blockIdx.x, t = threadIdx.x;  // 128 threads
    __shared__ float red[128];
    float s = 0.f;
    for (int k = t; k < FF; k += 128) { float v = inp[b * FF + k]; s += v * v; }
    red[t] = s; __syncthreads();
    for (int o = 64; o > 0; o >>= 1) { if (t < o) red[t] += red[t + o]; __syncthreads(); }
    float inv = 1.f / fmaxf(sqrtf(red[0]), 1e-5f);
    for (int k = t; k < FF; k += 128) {
        float e = inp[b * FF + k] * inv;
        g_emb[b * FF + k] = e;
        g_embh[b * FF + k] = __float2bfloat16(e);
    }
    if (t == 0) { g_rowsum1[b] = 0.f; g_rowsum2[b] = 0.f; }
}

// ---------------------------------------------------------------------------
// K2: virtual-prototype update for the 256 labeled rows (queue untouched)
__global__ void k_queue_update(const float* __restrict__ queue, const int* __restrict__ label) {
    int b = blockIdx.x, t = threadIdx.x;  // 128 threads
    int lb = label[b];
    const float* q = queue + (size_t)lb * FF;
    const float* e = g_emb + b * FF;
    __shared__ float r1[128], r2[128];
    float sq = 0.f, dd = 0.f;
    for (int k = t; k < FF; k += 128) { float qa = q[k], ea = e[k]; sq += qa * qa; dd += qa * ea; }
    r1[t] = sq; r2[t] = dd; __syncthreads();
    for (int o = 64; o > 0; o >>= 1) {
        if (t < o) { r1[t] += r1[t + o]; r2[t] += r2[t + o]; }
        __syncthreads();
    }
    float invold = 1.f / fmaxf(sqrtf(r1[0]), 1e-12f);
    float drift = r2[0];
    float factor = drift / (1.f + fabsf(drift));
    __syncthreads();
    float sn = 0.f;
    for (int k = t; k < FF; k += 128) {
        float v = factor * q[k] + (1.f - factor) * e[k];
        sn += v * v;
    }
    r1[t] = sn; __syncthreads();
    for (int o = 64; o > 0; o >>= 1) { if (t < o) r1[t] += r1[t + o]; __syncthreads(); }
    float invnew = 1.f / fmaxf(sqrtf(r1[0]), 1e-12f);
    for (int k = t; k < FF; k += 128) {
        float v = factor * q[k] + (1.f - factor) * e[k];
        g_newq[b * FF + k] = v * invnew;
        g_oldn[b * FF + k] = q[k] * invold;
    }
    if (t == 0) {
        int own = 1;
        for (int j = b + 1; j < BB; j++) if (label[j] == lb) { own = 0; break; }
        g_owner[b] = own;
    }
}

// ---------------------------------------------------------------------------
// K3: HMMA GEMM with fused norm + exp + rowsum.  pass = blockIdx.z
__global__ void __launch_bounds__(512)
k_gemm(const float* __restrict__ Wt, const float* __restrict__ Qu, const int* __restrict__ label) {
    __shared__ __nv_bfloat16 As[BM * STR];
    __shared__ __nv_bfloat16 Bs[BN * STR];
    __shared__ float s_nsq[BN];
    __shared__ float s_invn[BN];
    __shared__ float s_row[BM];
    __shared__ int s_lab[BM];

    int pass = blockIdx.z;
    const float* W = pass ? Qu : Wt;
    int m0 = blockIdx.y * BM;
    int c0 = blockIdx.x * BN;
    int tid = threadIdx.x;
    int wid = tid >> 5, lane = tid & 31;
    int mw = wid >> 2, nw = wid & 3;     // 4x4 warp grid, 32x32 warp tile

    if (tid < BM) { s_row[tid] = 0.f; s_lab[tid] = label[m0 + tid]; }

    int lr = tid >> 2;                   // load row 0..127
    int lq = tid & 3;                    // quarter: 16 elems each
    int gBr = c0 + lr;
    bool bok = gBr < CC;

    float d[2][4][4];
#pragma unroll
    for (int i = 0; i < 2; i++)
#pragma unroll
        for (int j = 0; j < 4; j++)
#pragma unroll
            for (int e = 0; e < 4; e++) d[i][j][e] = 0.f;

    float ssacc = 0.f;
    uint32_t aAs = s2u(As), aBs = s2u(Bs);
    int rin = lane & 7, seg = lane >> 3;

    uint4 pa0, pa1;
    float4 pb[4];
    {   // prefetch chunk 0
        const uint4* p = (const uint4*)(g_embh + (size_t)(m0 + lr) * FF + lq * 16);
        pa0 = p[0]; pa1 = p[1];
        if (bok) {
            const float4* q = (const float4*)(W + (size_t)gBr * FF + lq * 16);
            pb[0] = q[0]; pb[1] = q[1]; pb[2] = q[2]; pb[3] = q[3];
        } else {
            pb[0] = pb[1] = pb[2] = pb[3] = make_float4(0.f, 0.f, 0.f, 0.f);
        }
    }

    for (int c = 0; c < NCH; c++) {
        __syncthreads();   // previous compute finished; smem reusable
        {   // store A
            uint4* pa = (uint4*)(As + lr * STR + lq * 16);
            pa[0] = pa0; pa[1] = pa1;
            float ss = 0.f;
#pragma unroll
            for (int i = 0; i < 4; i++)
                ss += pb[i].x * pb[i].x + pb[i].y * pb[i].y + pb[i].z * pb[i].z + pb[i].w * pb[i].w;
            ssacc += ss;
            uint4 q0, q1;
            q0.x = pk(pb[0].x, pb[0].y); q0.y = pk(pb[0].z, pb[0].w);
            q0.z = pk(pb[1].x, pb[1].y); q0.w = pk(pb[1].z, pb[1].w);
            q1.x = pk(pb[2].x, pb[2].y); q1.y = pk(pb[2].z, pb[2].w);
            q1.z = pk(pb[3].x, pb[3].y); q1.w = pk(pb[3].z, pb[3].w);
            uint4* pbs = (uint4*)(Bs + lr * STR + lq * 16);
            pbs[0] = q0; pbs[1] = q1;
        }
        __syncthreads();
        if (c + 1 < NCH) {  // prefetch next chunk (overlaps compute below)
            const uint4* p = (const uint4*)(g_embh + (size_t)(m0 + lr) * FF + (c + 1) * KC + lq * 16);
            pa0 = p[0]; pa1 = p[1];
            if (bok) {
                const float4* q = (const float4*)(W + (size_t)gBr * FF + (c + 1) * KC + lq * 16);
                pb[0] = q[0]; pb[1] = q[1]; pb[2] = q[2]; pb[3] = q[3];
            }
        }
#pragma unroll
        for (int ks = 0; ks < 4; ks++) {
            int kk = ks * 16;
            uint32_t af[2][4];
#pragma unroll
            for (int mf = 0; mf < 2; mf++) {
                int row = mw * 32 + mf * 16 + (seg & 1) * 8 + rin;
                int col = kk + (seg >> 1) * 8;
                LDSM4(af[mf][0], af[mf][1], af[mf][2], af[mf][3],
                      aAs + (uint32_t)(row * STR + col) * 2);
            }
            uint32_t bfr[4][2];
#pragma unroll
            for (int bh = 0; bh < 2; bh++) {
                int row = nw * 32 + bh * 16 + (seg >> 1) * 8 + rin;
                int col = kk + (seg & 1) * 8;
                uint32_t r0, r1, r2, r3;
                LDSM4(r0, r1, r2, r3, aBs + (uint32_t)(row * STR + col) * 2);
                bfr[bh * 2][0] = r0;     bfr[bh * 2][1] = r1;
                bfr[bh * 2 + 1][0] = r2; bfr[bh * 2 + 1][1] = r3;
            }
#pragma unroll
            for (int mf = 0; mf < 2; mf++)
#pragma unroll
                for (int nt = 0; nt < 4; nt++) MMA16816(d[mf][nt], af[mf], bfr[nt]);
        }
    }

    ssacc += __shfl_xor_sync(0xffffffffu, ssacc, 1);
    ssacc += __shfl_xor_sync(0xffffffffu, ssacc, 2);
    if (lq == 0) s_nsq[lr] = ssacc;
    __syncthreads();
    if (tid < BN) s_invn[tid] = 1.f / fmaxf(sqrtf(s_nsq[tid]), pass ? 1e-12f : 1e-5f);
    __syncthreads();

    // epilogue — exp via fexp2 on the fma pipe (no MUFU)
    int g4 = lane >> 2, j4 = lane & 3;
#pragma unroll
    for (int mf = 0; mf < 2; mf++) {
        int ra = mw * 32 + mf * 16 + g4;
        int rb = ra + 8;
        int la = s_lab[ra], lb = s_lab[rb];
        float sa = 0.f, sb = 0.f;
#pragma unroll
        for (int nt = 0; nt < 4; nt++) {
            int cbase = nw * 32 + nt * 8 + j4 * 2;
#pragma unroll
            for (int e = 0; e < 2; e++) {
                int lc = cbase + e;
                int gc = c0 + lc;
                if (gc < CC) {
                    float iv = s_invn[lc];
                    float cva = d[mf][nt][e] * iv;
                    if (pass == 0 && gc == la) g_pos1[m0 + ra] = fexp2(-KE * (cva - MMAR));
                    else sa += fexp2(KE * cva);
                    float cvb = d[mf][nt][e + 2] * iv;
                    if (pass == 0 && gc == lb) g_pos1[m0 + rb] = fexp2(-KE * (cvb - MMAR));
                    else sb += fexp2(KE * cvb);
                }
            }
        }
        sa += __shfl_xor_sync(0xffffffffu, sa, 1);
        sa += __shfl_xor_sync(0xffffffffu, sa, 2);
        sb += __shfl_xor_sync(0xffffffffu, sb, 1);
        sb += __shfl_xor_sync(0xffffffffu, sb, 2);
        if (j4 == 0) { atomicAdd(&s_row[ra], sa); atomicAdd(&s_row[rb], sb); }
    }
    __syncthreads();
    if (tid < BM)
        atomicAdd(pass ? &g_rowsum2[m0 + tid] : &g_rowsum1[m0 + tid], s_row[tid]);
}

// ---------------------------------------------------------------------------
// K5: queue-column fixups — 4 concurrent j-pairs per warp, coalesced float4
__global__ void k_correct(const int* __restrict__ label) {
    int b = blockIdx.x;
    int tid = threadIdx.x;  // 256 = 8 warps
    int w = tid >> 5, lane = tid & 31;
    __shared__ float4 es[FF / 4];
    __shared__ float wneg[8];
    for (int k = tid; k < FF / 4; k += 256)
        es[k] = ((const float4*)(g_emb + (size_t)b * FF))[k];
    __syncthreads();
    int mylab = label[b];
    float negd = 0.f;
#pragma unroll 1
    for (int it = 0; it < 8; it++) {
        int j0 = (w + 8 * it) * 4;
        float doo[4] = {0.f, 0.f, 0.f, 0.f}, dnn[4] = {0.f, 0.f, 0.f, 0.f};
#pragma unroll
        for (int kit = 0; kit < 4; kit++) {
            int k4 = lane + 32 * kit;
            float4 e = es[k4];
#pragma unroll
            for (int s = 0; s < 4; s++) {
                float4 o4 = ((const float4*)(g_oldn + (size_t)(j0 + s) * FF))[k4];
                float4 n4 = ((const float4*)(g_newq + (size_t)(j0 + s) * FF))[k4];
                doo[s] += e.x * o4.x + e.y * o4.y + e.z * o4.z + e.w * o4.w;
                dnn[s] += e.x * n4.x + e.y * n4.y + e.z * n4.z + e.w * n4.w;
            }
        }
#pragma unroll
        for (int o = 16; o > 0; o >>= 1)
#pragma unroll
            for (int s = 0; s < 4; s++) {
                doo[s] += __shfl_xor_sync(0xffffffffu, doo[s], o);
                dnn[s] += __shfl_xor_sync(0xffffffffu, dnn[s], o);
            }
        if (lane < 4) {
            int j = j0 + lane;
            if (g_owner[j]) {
                negd -= __expf(SSC * doo[lane]);
                if (label[j] == mylab) g_pos2[b] = __expf(-SSC * (1.f - KVP) * dnn[lane]);
                else negd += __expf(SSC * dnn[lane]);
            }
        }
    }
    negd += __shfl_xor_sync(0xffffffffu, negd, 1);
    negd += __shfl_xor_sync(0xffffffffu, negd, 2);
    if (lane == 0) wneg[w] = negd;
    __syncthreads();
    if (tid == 0) {
        float s = 0.f;
        for (int i = 0; i < 8; i++) s += wneg[i];
        atomicAdd(&g_rowsum2[b], s);
    }
}

// ---------------------------------------------------------------------------
// K6: EPL loss
__global__ void k_final(float* __restrict__ out) {
    int t = threadIdx.x;  // 256
    __shared__ float red[256];
    float v = log1pf(g_rowsum1[t] * g_pos1[t]) + log1pf(g_rowsum2[t] * g_pos2[t]);
    red[t] = v; __syncthreads();
    for (int o = 128; o > 0; o >>= 1) { if (t < o) red[t] += red[t + o]; __syncthreads(); }
    if (t == 0) out[0] = red[0] / (2.f * BB);
}

// ---------------------------------------------------------------------------
extern "C" void kernel_launch(void* const* d_in, const int* in_sizes, int n_in,
                              void* d_out, int out_size) {
    const float* inp    = (const float*)d_in[0];
    const float* weight = (const float*)d_in[1];
    const float* queue  = (const float*)d_in[2];
    const int*   label  = (const int*)d_in[3];
    float* out = (float*)d_out;

    k_norm_input<<<BB, 128>>>(inp);
    k_queue_update<<<BB, 128>>>(queue, label);
    dim3 grid(NTILES, BB / BM, 2);
    k_gemm<<<grid, 512>>>(weight, queue, label);
    k_correct<<<BB, 256>>>(label);
    k_final<<<1, 256>>>(out);
}